// round 14
// baseline (speedup 1.0000x reference)
#include <cuda_runtime.h>
#include <math.h>
#include <stdint.h>

#define NN 20000
#define NE 640000
#define DD 128
#define OUTD 256
#define BBATCH 64
#define HOUT 62
#define MPI (HOUT*HOUT)   // 3844 pixels per image
#define MT 31             // M-tiles of 128 per image
#define KTOT 1152
#define KC 16             // K chunk
#define NCHUNK (KTOT/KC)  // 72
#define ASTRIDE 20        // floats per A row (80B): conflict-free STS.128 + ldmatrix
#define BUFF (128*ASTRIDE)

// ---------------- scratch ----------------
__device__ __align__(16) float g_acc[8];               // [slot]{ ||v||^2, ||Wv||^2 }
__device__ __align__(16) float g_sv[3 * 1152];         // v = W^T u per slot
__device__ __align__(16) float g_wfrag[KTOT * DD];     // conv W in mma-fragment order, tf32-rna
__device__ __align__(16) float g_fcvT[512 * OUTD];
__device__ __align__(16) float g_fctT[DD * OUTD];
__device__ __align__(16) float g_partial[BBATCH * MT * 4 * DD];
__device__ __align__(16) float g_pool_vis[BBATCH * DD * 4];
__device__ __align__(16) float g_topo_part[BBATCH * 4 * DD];
__device__ __align__(16) float g_deg[NN];
__device__ __align__(16) float g_dis[NN];
__device__ __align__(16) float g_xw[NN * DD];
__device__ __align__(16) float g_h[NN * DD];

__device__ __forceinline__ int clampi(int v, int lo, int hi) {
    return v < lo ? lo : (v > hi ? hi : v);
}
__device__ __forceinline__ uint32_t f2tf32(float f) {
    uint32_t u;
    asm("cvt.rna.tf32.f32 %0, %1;" : "=r"(u) : "f"(f));
    return u;
}
__device__ __forceinline__ uint32_t smem_u32(const void* p) {
    uint32_t a;
    asm("{ .reg .u64 t; cvta.to.shared.u64 t, %1; cvt.u32.u64 %0, t; }" : "=r"(a) : "l"(p));
    return a;
}
__device__ __forceinline__ void mma_tf32(float* d, const uint32_t* a, const uint32_t* b) {
    asm volatile(
        "mma.sync.aligned.m16n8k8.row.col.f32.tf32.tf32.f32 "
        "{%0,%1,%2,%3}, {%4,%5,%6,%7}, {%8,%9}, {%0,%1,%2,%3};"
        : "+f"(d[0]), "+f"(d[1]), "+f"(d[2]), "+f"(d[3])
        : "r"(a[0]), "r"(a[1]), "r"(a[2]), "r"(a[3]), "r"(b[0]), "r"(b[1]));
}
__device__ __forceinline__ void ldsm_x4(uint32_t* r, uint32_t addr) {
    asm volatile("ldmatrix.sync.aligned.m8n8.x4.shared.b16 {%0,%1,%2,%3}, [%4];"
                 : "=r"(r[0]), "=r"(r[1]), "=r"(r[2]), "=r"(r[3]) : "r"(addr));
}
__device__ __forceinline__ void cp_async16(uint32_t dst, const void* src) {
    asm volatile("cp.async.cg.shared.global [%0], [%1], 16;"
                 :: "r"(dst), "l"(src) : "memory");
}
// sigma = s^2/(s+eps) with s = ||Wv||/(||v||+eps); returns 1/sigma
__device__ __forceinline__ float inv_sigma_from(int slot) {
    float vn = sqrtf(g_acc[slot * 2 + 0]);
    float tn = sqrtf(g_acc[slot * 2 + 1]);
    float s = tn / (vn + 1e-12f);
    float sigma = s * s / (s + 1e-12f);
    return 1.0f / sigma;
}

// ---------------- prep: zero scratch ----------------
__global__ void prep_kernel() {
    int idx = blockIdx.x * 256 + threadIdx.x;
    if (idx < NN * DD) g_h[idx] = 0.f;
    if (idx < NN) g_deg[idx] = 1.0f;     // self loop
    if (idx < 8) g_acc[idx] = 0.f;
}

// ---------------- spectral norm: v = W^T u (coalesced), ||v||^2 ----------------
__global__ void sigma_v(const float* __restrict__ W, const float* __restrict__ u,
                        int R, int C, int slot) {
    int j = blockIdx.x * 256 + threadIdx.x;
    if (j >= C) return;
    float t = 0.f;
    for (int i = 0; i < R; i++) t += W[i * C + j] * u[i];
    g_sv[slot * 1152 + j] = t;
    atomicAdd(&g_acc[slot * 2 + 0], t * t);
}

// ---------------- spectral norm: ||W v||^2, warp per row ----------------
__global__ void sigma_t(const float* __restrict__ W, int R, int C, int slot) {
    int warp = threadIdx.x >> 5, lane = threadIdx.x & 31;
    int i = blockIdx.x * 8 + warp;
    if (i >= R) return;
    const float* sv = &g_sv[slot * 1152];
    float t = 0.f;
    for (int j = lane; j < C; j += 32) t += W[i * C + j] * sv[j];
#pragma unroll
    for (int o = 16; o > 0; o >>= 1) t += __shfl_xor_sync(0xFFFFFFFFu, t, o);
    if (lane == 0) atomicAdd(&g_acc[slot * 2 + 1], t * t);
}

// ---------------- conv weights -> mma fragment order (unscaled, tf32-rna) --------
__global__ void wfrag_kernel(const float* __restrict__ src) {
    int idx = blockIdx.x * 256 + threadIdx.x;
    if (idx >= KTOT * DD) return;
    int w = idx & 3;
    int lane = (idx >> 2) & 31;
    int ks = (idx >> 7) & 1;
    int prg = (idx >> 8) & 7;
    int ch = idx >> 11;
    int cout = prg * 16 + ((w >> 1) << 3) + (lane >> 2);
    int k = ch * 16 + ks * 8 + ((w & 1) << 2) + (lane & 3);
    g_wfrag[idx] = __uint_as_float(f2tf32(src[cout * KTOT + k]));
}

// ---------------- fc weight transpose + scale (inline sigma) ----------------
__global__ void transpose_fcv(const float* __restrict__ src) {
    int idx = blockIdx.x * 256 + threadIdx.x;
    if (idx >= 256 * 512) return;
    int r = idx / 512, c = idx - r * 512;
    g_fcvT[c * 256 + r] = src[idx] * inv_sigma_from(1);
}
__global__ void transpose_fct(const float* __restrict__ src) {
    int idx = blockIdx.x * 256 + threadIdx.x;
    if (idx >= 256 * 128) return;
    int r = idx / 128, c = idx - r * 128;
    g_fctT[c * 256 + r] = src[idx] * inv_sigma_from(2);
}

// ---------------- degree + normalization ----------------
__global__ void deg_kernel(const int* __restrict__ ei) {
    int e = blockIdx.x * 256 + threadIdx.x;
    if (e < NE) atomicAdd(&g_deg[clampi(ei[NE + e], 0, NN - 1)], 1.0f);
}
__global__ void dis_kernel() {
    int i = blockIdx.x * 256 + threadIdx.x;
    if (i < NN) g_dis[i] = rsqrtf(g_deg[i]);
}

// ---------------- xw = topo @ gcn_w ----------------
__global__ void xw_kernel(const float* __restrict__ topo, const float* __restrict__ gw) {
    __shared__ float st[8 * 128];
    int n0 = blockIdx.x * 8;
    int tid = threadIdx.x;
#pragma unroll
    for (int i = 0; i < 8; i++) st[i * 128 + tid] = topo[(n0 + i) * 128 + tid];
    __syncthreads();
    float acc[8];
#pragma unroll
    for (int r = 0; r < 8; r++) acc[r] = 0.f;
    for (int k = 0; k < 128; k++) {
        float w = gw[k * 128 + tid];
#pragma unroll
        for (int r = 0; r < 8; r++) acc[r] += st[r * 128 + k] * w;
    }
#pragma unroll
    for (int r = 0; r < 8; r++) g_xw[(n0 + r) * 128 + tid] = acc[r];
}

// ---------------- edge scatter via red.v4 ----------------
__global__ void scatter_kernel(const int* __restrict__ ei) {
    int e = blockIdx.x * 8 + (threadIdx.x >> 5);
    if (e >= NE) return;
    int lane = threadIdx.x & 31;
    int src = clampi(ei[e], 0, NN - 1);
    int dst = clampi(ei[NE + e], 0, NN - 1);
    float nrm = g_dis[src] * g_dis[dst];
    float4 v = *(const float4*)&g_xw[src * 128 + lane * 4];
    asm volatile("red.global.add.v4.f32 [%0], {%1, %2, %3, %4};"
                 :: "l"(&g_h[dst * 128 + lane * 4]),
                    "f"(v.x * nrm), "f"(v.y * nrm), "f"(v.z * nrm), "f"(v.w * nrm)
                 : "memory");
}

// ---------------- topo pool ----------------
__global__ void topo_pool_kernel(const int* __restrict__ batch, const float* __restrict__ gb) {
    int b = blockIdx.x;
    int stripe = blockIdx.y;
    int c = threadIdx.x;

    int lo = 0, hi = NN;
    while (lo < hi) { int mid = (lo + hi) >> 1; if (batch[mid] < b) lo = mid + 1; else hi = mid; }
    int s = lo;
    lo = s; hi = NN;
    while (lo < hi) { int mid = (lo + hi) >> 1; if (batch[mid] < b + 1) lo = mid + 1; else hi = mid; }
    int e = lo;

    float bias = gb[c];
    float m = -INFINITY;
    for (int n = s + stripe; n < e; n += 4) {
        float d = g_dis[n];
        float val = g_h[n * 128 + c] + d * d * g_xw[n * 128 + c] + bias;
        val = (val >= 0.f) ? val : 0.2f * val;
        m = fmaxf(m, val);
    }
    g_topo_part[(b * 4 + stripe) * 128 + c] = m;
}

// ---------------- conv3x3: tf32 mma, 4 warps of 64x64 (less smem traffic/MMA) -----
// block 128 pixels x 128 cout; 128 threads
__global__ void __launch_bounds__(128, 2)
conv_mma_kernel(const float* __restrict__ vis) {
    __shared__ __align__(16) float sA[2][BUFF];     // 20KB
    __shared__ __align__(16) uint4 sB[2][512];      // 16KB (fragment order, linear)
    __shared__ int skoff[KTOT];
    __shared__ unsigned char srowreg[128];

    int tid = threadIdx.x;
    int warp = tid >> 5, lane = tid & 31;
    int wm = warp & 1;        // rows 64*wm
    int wn = warp >> 1;       // cols 64*wn
    int gq = lane >> 2, tg = lane & 3;

    int img = blockIdx.x / MT;
    int mt = blockIdx.x - img * MT;
    int m0 = mt * 128;

    for (int k = tid; k < KTOT; k += 128) {
        int ci = k / 9, rem = k - ci * 9, ky = rem / 3, kx = rem - ky * 3;
        skoff[k] = ci * 4096 + ky * 64 + kx;
    }
    {
        int s = m0 + tid;
        unsigned char r = 4;
        if (s < MPI) {
            int yy = s / HOUT, xx = s - yy * HOUT;
            r = (unsigned char)(((yy >= 31) ? 2 : 0) + ((xx >= 31) ? 1 : 0));
        }
        srowreg[tid] = r;
    }

    // A gather: pixel p = tid, all 16 k values per chunk
    int p = tid;
    int s = m0 + p;
    bool valid = (s < MPI);
    int y = valid ? (s / HOUT) : 0;
    int x = valid ? (s - y * HOUT) : 0;
    const float* base = vis + (size_t)img * 128 * 4096 + y * 64 + x;
    float* aSm = &sA[0][p * ASTRIDE];

    const uint4* wf4 = (const uint4*)g_wfrag;
    int pbase = wn * 256 + lane;   // uint4 index within a chunk's 512

    uint32_t sa0 = smem_u32(sA);
    uint32_t sbB = smem_u32(sB);
    uint32_t bDst = sbB + tid * 16;
    const uint32_t bStageBytes = 512 * 16;

    int mR = lane >> 3, rr = lane & 7;
    uint32_t offA[4];
#pragma unroll
    for (int mi = 0; mi < 4; mi++)
        offA[mi] = (((wm * 64 + mi * 16 + (mR & 1) * 8 + rr) * ASTRIDE + (mR >> 1) * 4) << 2);

    float acc[4][8][4];
#pragma unroll
    for (int mi = 0; mi < 4; mi++)
#pragma unroll
        for (int ni = 0; ni < 8; ni++)
#pragma unroll
            for (int c = 0; c < 4; c++) acc[mi][ni][c] = 0.f;

    float pa[16];
    __syncthreads();   // tables ready

    // prologue: B chunk0 via cp.async (4x16B per thread); A chunk0 regs -> stage 0
#pragma unroll
    for (int j = 0; j < 4; j++)
        cp_async16(bDst + j * 2048, wf4 + tid + j * 128);
    asm volatile("cp.async.commit_group;" ::: "memory");
#pragma unroll
    for (int i = 0; i < 16; i++) pa[i] = valid ? base[skoff[i]] : 0.f;
#pragma unroll
    for (int j = 0; j < 4; j++)
        *(float4*)(aSm + j * 4) = make_float4(pa[j * 4], pa[j * 4 + 1], pa[j * 4 + 2], pa[j * 4 + 3]);

    for (int ch = 0; ch < NCHUNK; ch++) {
        asm volatile("cp.async.wait_group 0;" ::: "memory");
        __syncthreads();   // A(ch)+B(ch) visible; stage (ch+1)&1 free

        if (ch + 1 < NCHUNK) {
            uint32_t bd = bDst + ((ch + 1) & 1) * bStageBytes;
            const uint4* ws = wf4 + (ch + 1) * 512 + tid;
#pragma unroll
            for (int j = 0; j < 4; j++) cp_async16(bd + j * 2048, ws + j * 128);
            asm volatile("cp.async.commit_group;" ::: "memory");
            int kg0 = (ch + 1) * KC;
#pragma unroll
            for (int i = 0; i < 16; i++) pa[i] = valid ? base[skoff[kg0 + i]] : 0.f;
        }

        uint32_t stA = (ch & 1) * (BUFF << 2);
        const uint4* sBc = sB[ch & 1];
#pragma unroll
        for (int ks = 0; ks < 2; ks++) {
            uint32_t a[4][4];
            uint4 q[4];
#pragma unroll
            for (int pr = 0; pr < 4; pr++) q[pr] = sBc[pbase + pr * 64 + ks * 32];
#pragma unroll
            for (int mi = 0; mi < 4; mi++) ldsm_x4(a[mi], sa0 + offA[mi] + stA + ks * 32);
#pragma unroll
            for (int mi = 0; mi < 4; mi++)
#pragma unroll
                for (int pr = 0; pr < 4; pr++) {
                    mma_tf32(acc[mi][pr * 2 + 0], a[mi], (const uint32_t*)&q[pr]);
                    mma_tf32(acc[mi][pr * 2 + 1], a[mi], ((const uint32_t*)&q[pr]) + 2);
                }
        }

        if (ch + 1 < NCHUNK) {
            float* dA = aSm + ((ch + 1) & 1) * BUFF;
#pragma unroll
            for (int j = 0; j < 4; j++)
                *(float4*)(dA + j * 4) = make_float4(pa[j * 4], pa[j * 4 + 1], pa[j * 4 + 2], pa[j * 4 + 3]);
        }
    }
    __syncthreads();   // all MMAs done before epilogue overlays sA

    // ---------------- epilogue: raw region max, 4 column passes ----------------
    float* sm = &sA[0][0];   // overlay [128][33] = 4224 <= 2*BUFF = 5120
#pragma unroll
    for (int q = 0; q < 4; q++) {
        if ((q >> 1) == wn) {
            int ni0 = (q & 1) * 4;
#pragma unroll
            for (int mi = 0; mi < 4; mi++) {
#pragma unroll
                for (int nj = 0; nj < 4; nj++) {
                    int ni = ni0 + nj;
                    int colg = wn * 64 + ni * 8 + 2 * tg;
                    int colp = (colg - q * 32);
                    int r0 = wm * 64 + mi * 16 + gq;
#pragma unroll
                    for (int cc = 0; cc < 2; cc++) {
                        sm[r0 * 33 + colp + cc] = acc[mi][ni][cc];
                        sm[(r0 + 8) * 33 + colp + cc] = acc[mi][ni][2 + cc];
                    }
                }
            }
        }
        __syncthreads();
        {
            int ccol = tid & 31;
            int myreg = tid >> 5;
            float mx = -INFINITY;
            for (int row = 0; row < 128; row++) {
                float v = sm[row * 33 + ccol];
                mx = (srowreg[row] == (unsigned char)myreg) ? fmaxf(mx, v) : mx;
            }
            g_partial[((img * MT + mt) * 4 + myreg) * 128 + q * 32 + ccol] = mx;
        }
        __syncthreads();
    }
}

// ---------------- reduce partials; apply 1/sigma, bias, leaky ----------------
__global__ void vis_reduce_kernel(const float* __restrict__ cb) {
    int img = blockIdx.x;
    int o = threadIdx.x;    // 512
    int r = o >> 7;
    int col = o & 127;
    float m = -INFINITY;
    for (int mt = 0; mt < MT; mt++)
        m = fmaxf(m, g_partial[((img * MT + mt) * 4 + r) * 128 + col]);
    float v = m * inv_sigma_from(0) + cb[col];
    v = (v >= 0.f) ? v : 0.2f * v;
    g_pool_vis[img * 512 + col * 4 + r] = v;
}

// ---------------- vis score ----------------
__global__ void vis_score_kernel(const float* __restrict__ fcvb, float* __restrict__ out) {
    __shared__ float xs[512];
    int b = blockIdx.x, tid = threadIdx.x;
    for (int i = tid; i < 512; i += 256) xs[i] = g_pool_vis[b * 512 + i];
    __syncthreads();
    float acc = fcvb[tid];
    for (int j = 0; j < 512; j++) acc += xs[j] * g_fcvT[j * OUTD + tid];
    out[b * OUTD + tid] = acc;
}

// ---------------- topo score ----------------
__global__ void topo_score_kernel(const float* __restrict__ fctb, float* __restrict__ out) {
    __shared__ float xs[128];
    int b = blockIdx.x, tid = threadIdx.x;
    if (tid < 128) {
        float m = g_topo_part[(b * 4 + 0) * 128 + tid];
        m = fmaxf(m, g_topo_part[(b * 4 + 1) * 128 + tid]);
        m = fmaxf(m, g_topo_part[(b * 4 + 2) * 128 + tid]);
        m = fmaxf(m, g_topo_part[(b * 4 + 3) * 128 + tid]);
        xs[tid] = m;
    }
    __syncthreads();
    float acc = fctb[tid];
    for (int j = 0; j < 128; j++) acc += xs[j] * g_fctT[j * OUTD + tid];
    out[BBATCH * OUTD + b * OUTD + tid] = acc;
}

// ---------------- launch (conv 4th: ncu lands there) ----------------
extern "C" void kernel_launch(void* const* d_in, const int* in_sizes, int n_in,
                              void* d_out, int out_size) {
    const float* vis    = (const float*)d_in[0];
    const float* topo   = (const float*)d_in[1];
    const int*   ei     = (const int*)d_in[2];
    const int*   batch  = (const int*)d_in[3];
    const float* conv_w = (const float*)d_in[4];
    const float* conv_b = (const float*)d_in[5];
    const float* conv_u = (const float*)d_in[6];
    const float* fcv_w  = (const float*)d_in[7];
    const float* fcv_b  = (const float*)d_in[8];
    const float* fcv_u  = (const float*)d_in[9];
    const float* gcn_w  = (const float*)d_in[10];
    const float* gcn_b  = (const float*)d_in[11];
    const float* fct_w  = (const float*)d_in[12];
    const float* fct_b  = (const float*)d_in[13];
    const float* fct_u  = (const float*)d_in[14];
    float*       out    = (float*)d_out;

    // 1..3
    prep_kernel<<<(NN * DD + 255) / 256, 256>>>();
    wfrag_kernel<<<(KTOT * DD + 255) / 256, 256>>>(conv_w);
    sigma_v<<<(1152 + 255) / 256, 256>>>(conv_w, conv_u, 128, 1152, 0);
    // 4: conv (profiled slot; independent of sigma)
    conv_mma_kernel<<<BBATCH * MT, 128>>>(vis);

    sigma_t<<<(128 + 7) / 8, 256>>>(conv_w, 128, 1152, 0);

    // topo head
    deg_kernel<<<(NE + 255) / 256, 256>>>(ei);
    dis_kernel<<<(NN + 255) / 256, 256>>>();
    xw_kernel<<<NN / 8, 128>>>(topo, gcn_w);
    scatter_kernel<<<NE / 8, 256>>>(ei);

    // fc sigmas + transposes
    sigma_v<<<(512 + 255) / 256, 256>>>(fcv_w, fcv_u, 256, 512, 1);
    sigma_t<<<(256 + 7) / 8, 256>>>(fcv_w, 256, 512, 1);
    sigma_v<<<(128 + 255) / 256, 256>>>(fct_w, fct_u, 256, 128, 2);
    sigma_t<<<(256 + 7) / 8, 256>>>(fct_w, 256, 128, 2);
    transpose_fcv<<<(256 * 512 + 255) / 256, 256>>>(fcv_w);
    transpose_fct<<<(256 * 128 + 255) / 256, 256>>>(fct_w);

    vis_reduce_kernel<<<BBATCH, 512>>>(conv_b);
    {
        dim3 g(BBATCH, 4);
        topo_pool_kernel<<<g, 128>>>(batch, gcn_b);
    }

    vis_score_kernel<<<BBATCH, 256>>>(fcv_b, out);
    topo_score_kernel<<<BBATCH, 256>>>(fct_b, out);
}

// round 15
// speedup vs baseline: 1.1059x; 1.1059x over previous
#include <cuda_runtime.h>
#include <math.h>
#include <stdint.h>

#define NN 20000
#define NE 640000
#define DD 128
#define OUTD 256
#define BBATCH 64
#define HOUT 62
#define MPI (HOUT*HOUT)   // 3844 pixels per image
#define MT 31             // M-tiles of 128 per image
#define KTOT 1152
#define KC 16             // K chunk
#define NCHUNK (KTOT/KC)  // 72
#define ASTRIDE 20        // floats per A row (80B): conflict-free STS.128 + ldmatrix
#define BUFF (128*ASTRIDE)

// ---------------- scratch ----------------
__device__ __align__(16) float g_acc[8];               // [slot]{ ||v||^2, ||Wv||^2 }
__device__ __align__(16) float g_sv[3 * 1152];         // v = W^T u per slot
__device__ __align__(16) float g_wfrag[KTOT * DD];     // conv W in mma-fragment order, tf32-rna
__device__ __align__(16) float g_fcvT[512 * OUTD];
__device__ __align__(16) float g_fctT[DD * OUTD];
__device__ __align__(16) float g_partial[BBATCH * MT * 4 * DD];
__device__ __align__(16) float g_pool_vis[BBATCH * DD * 4];
__device__ __align__(16) float g_topo_part[BBATCH * 4 * DD];
__device__ __align__(16) float g_deg[NN];
__device__ __align__(16) float g_dis[NN];
__device__ __align__(16) float g_xw[NN * DD];
__device__ __align__(16) float g_h[NN * DD];

__device__ __forceinline__ int clampi(int v, int lo, int hi) {
    return v < lo ? lo : (v > hi ? hi : v);
}
__device__ __forceinline__ uint32_t f2tf32(float f) {
    uint32_t u;
    asm("cvt.rna.tf32.f32 %0, %1;" : "=r"(u) : "f"(f));
    return u;
}
__device__ __forceinline__ uint32_t smem_u32(const void* p) {
    uint32_t a;
    asm("{ .reg .u64 t; cvta.to.shared.u64 t, %1; cvt.u32.u64 %0, t; }" : "=r"(a) : "l"(p));
    return a;
}
__device__ __forceinline__ void mma_tf32(float* d, const uint32_t* a, const uint32_t* b) {
    asm volatile(
        "mma.sync.aligned.m16n8k8.row.col.f32.tf32.tf32.f32 "
        "{%0,%1,%2,%3}, {%4,%5,%6,%7}, {%8,%9}, {%0,%1,%2,%3};"
        : "+f"(d[0]), "+f"(d[1]), "+f"(d[2]), "+f"(d[3])
        : "r"(a[0]), "r"(a[1]), "r"(a[2]), "r"(a[3]), "r"(b[0]), "r"(b[1]));
}
__device__ __forceinline__ void ldsm_x4(uint32_t* r, uint32_t addr) {
    asm volatile("ldmatrix.sync.aligned.m8n8.x4.shared.b16 {%0,%1,%2,%3}, [%4];"
                 : "=r"(r[0]), "=r"(r[1]), "=r"(r[2]), "=r"(r[3]) : "r"(addr));
}
__device__ __forceinline__ void cp_async16(uint32_t dst, const void* src) {
    asm volatile("cp.async.cg.shared.global [%0], [%1], 16;"
                 :: "r"(dst), "l"(src) : "memory");
}
// sigma = s^2/(s+eps) with s = ||Wv||/(||v||+eps); returns 1/sigma
__device__ __forceinline__ float inv_sigma_from(int slot) {
    float vn = sqrtf(g_acc[slot * 2 + 0]);
    float tn = sqrtf(g_acc[slot * 2 + 1]);
    float s = tn / (vn + 1e-12f);
    float sigma = s * s / (s + 1e-12f);
    return 1.0f / sigma;
}

// ---------------- prep: zero scratch ----------------
__global__ void prep_kernel() {
    int idx = blockIdx.x * 256 + threadIdx.x;
    if (idx < NN * DD) g_h[idx] = 0.f;
    if (idx < NN) g_deg[idx] = 1.0f;     // self loop
    if (idx < 8) g_acc[idx] = 0.f;
}

// ---------------- spectral norm: v = W^T u (coalesced), ||v||^2 ----------------
__global__ void sigma_v(const float* __restrict__ W, const float* __restrict__ u,
                        int R, int C, int slot) {
    int j = blockIdx.x * 256 + threadIdx.x;
    if (j >= C) return;
    float t = 0.f;
    for (int i = 0; i < R; i++) t += W[i * C + j] * u[i];
    g_sv[slot * 1152 + j] = t;
    atomicAdd(&g_acc[slot * 2 + 0], t * t);
}

// ---------------- spectral norm: ||W v||^2, warp per row ----------------
__global__ void sigma_t(const float* __restrict__ W, int R, int C, int slot) {
    int warp = threadIdx.x >> 5, lane = threadIdx.x & 31;
    int i = blockIdx.x * 8 + warp;
    if (i >= R) return;
    const float* sv = &g_sv[slot * 1152];
    float t = 0.f;
    for (int j = lane; j < C; j += 32) t += W[i * C + j] * sv[j];
#pragma unroll
    for (int o = 16; o > 0; o >>= 1) t += __shfl_xor_sync(0xFFFFFFFFu, t, o);
    if (lane == 0) atomicAdd(&g_acc[slot * 2 + 1], t * t);
}

// ---------------- conv weights -> mma fragment order (unscaled, tf32-rna) --------
__global__ void wfrag_kernel(const float* __restrict__ src) {
    int idx = blockIdx.x * 256 + threadIdx.x;
    if (idx >= KTOT * DD) return;
    int w = idx & 3;
    int lane = (idx >> 2) & 31;
    int ks = (idx >> 7) & 1;
    int prg = (idx >> 8) & 7;
    int ch = idx >> 11;
    int cout = prg * 16 + ((w >> 1) << 3) + (lane >> 2);
    int k = ch * 16 + ks * 8 + ((w & 1) << 2) + (lane & 3);
    g_wfrag[idx] = __uint_as_float(f2tf32(src[cout * KTOT + k]));
}

// ---------------- fc weight transpose + scale (inline sigma) ----------------
__global__ void transpose_fcv(const float* __restrict__ src) {
    int idx = blockIdx.x * 256 + threadIdx.x;
    if (idx >= 256 * 512) return;
    int r = idx / 512, c = idx - r * 512;
    g_fcvT[c * 256 + r] = src[idx] * inv_sigma_from(1);
}
__global__ void transpose_fct(const float* __restrict__ src) {
    int idx = blockIdx.x * 256 + threadIdx.x;
    if (idx >= 256 * 128) return;
    int r = idx / 128, c = idx - r * 128;
    g_fctT[c * 256 + r] = src[idx] * inv_sigma_from(2);
}

// ---------------- degree + normalization ----------------
__global__ void deg_kernel(const int* __restrict__ ei) {
    int e = blockIdx.x * 256 + threadIdx.x;
    if (e < NE) atomicAdd(&g_deg[clampi(ei[NE + e], 0, NN - 1)], 1.0f);
}
__global__ void dis_kernel() {
    int i = blockIdx.x * 256 + threadIdx.x;
    if (i < NN) g_dis[i] = rsqrtf(g_deg[i]);
}

// ---------------- xw = topo @ gcn_w ----------------
__global__ void xw_kernel(const float* __restrict__ topo, const float* __restrict__ gw) {
    __shared__ float st[8 * 128];
    int n0 = blockIdx.x * 8;
    int tid = threadIdx.x;
#pragma unroll
    for (int i = 0; i < 8; i++) st[i * 128 + tid] = topo[(n0 + i) * 128 + tid];
    __syncthreads();
    float acc[8];
#pragma unroll
    for (int r = 0; r < 8; r++) acc[r] = 0.f;
    for (int k = 0; k < 128; k++) {
        float w = gw[k * 128 + tid];
#pragma unroll
        for (int r = 0; r < 8; r++) acc[r] += st[r * 128 + k] * w;
    }
#pragma unroll
    for (int r = 0; r < 8; r++) g_xw[(n0 + r) * 128 + tid] = acc[r];
}

// ---------------- edge scatter via red.v4 ----------------
__global__ void scatter_kernel(const int* __restrict__ ei) {
    int e = blockIdx.x * 8 + (threadIdx.x >> 5);
    if (e >= NE) return;
    int lane = threadIdx.x & 31;
    int src = clampi(ei[e], 0, NN - 1);
    int dst = clampi(ei[NE + e], 0, NN - 1);
    float nrm = g_dis[src] * g_dis[dst];
    float4 v = *(const float4*)&g_xw[src * 128 + lane * 4];
    asm volatile("red.global.add.v4.f32 [%0], {%1, %2, %3, %4};"
                 :: "l"(&g_h[dst * 128 + lane * 4]),
                    "f"(v.x * nrm), "f"(v.y * nrm), "f"(v.z * nrm), "f"(v.w * nrm)
                 : "memory");
}

// ---------------- topo pool ----------------
__global__ void topo_pool_kernel(const int* __restrict__ batch, const float* __restrict__ gb) {
    int b = blockIdx.x;
    int stripe = blockIdx.y;
    int c = threadIdx.x;

    int lo = 0, hi = NN;
    while (lo < hi) { int mid = (lo + hi) >> 1; if (batch[mid] < b) lo = mid + 1; else hi = mid; }
    int s = lo;
    lo = s; hi = NN;
    while (lo < hi) { int mid = (lo + hi) >> 1; if (batch[mid] < b + 1) lo = mid + 1; else hi = mid; }
    int e = lo;

    float bias = gb[c];
    float m = -INFINITY;
    for (int n = s + stripe; n < e; n += 4) {
        float d = g_dis[n];
        float val = g_h[n * 128 + c] + d * d * g_xw[n * 128 + c] + bias;
        val = (val >= 0.f) ? val : 0.2f * val;
        m = fmaxf(m, val);
    }
    g_topo_part[(b * 4 + stripe) * 128 + c] = m;
}

// ---------------- conv3x3: tf32 mma; A staged (STS.128+ldsm), B cp.async->LDS.128 --
// block 128 pixels x 128 cout; 8 warps 4x2 (warp tile 32x64)  [round-13 proven]
__global__ void __launch_bounds__(256, 2)
conv_mma_kernel(const float* __restrict__ vis) {
    __shared__ __align__(16) float sA[2][BUFF];     // 20KB
    __shared__ __align__(16) uint4 sB[2][512];      // 16KB (fragment order, linear)
    __shared__ int skoff[KTOT];
    __shared__ unsigned char srowreg[128];

    int tid = threadIdx.x;
    int warp = tid >> 5, lane = tid & 31;
    int wm = warp & 3;        // rows 32*wm
    int wn = warp >> 2;       // cols 64*wn
    int gq = lane >> 2, tg = lane & 3;

    int img = blockIdx.x / MT;
    int mt = blockIdx.x - img * MT;
    int m0 = mt * 128;

    for (int k = tid; k < KTOT; k += 256) {
        int ci = k / 9, rem = k - ci * 9, ky = rem / 3, kx = rem - ky * 3;
        skoff[k] = ci * 4096 + ky * 64 + kx;
    }
    if (tid < 128) {
        int s = m0 + tid;
        unsigned char r = 4;
        if (s < MPI) {
            int yy = s / HOUT, xx = s - yy * HOUT;
            r = (unsigned char)(((yy >= 31) ? 2 : 0) + ((xx >= 31) ? 1 : 0));
        }
        srowreg[tid] = r;
    }

    // A gather: pixel p = tid&127, k sub-range kb..kb+7
    int p = tid & 127;
    int kb = (tid >> 7) * 8;
    int s = m0 + p;
    bool valid = (s < MPI);
    int y = valid ? (s / HOUT) : 0;
    int x = valid ? (s - y * HOUT) : 0;
    const float* base = vis + (size_t)img * 128 * 4096 + y * 64 + x;
    float* aSm = &sA[0][p * ASTRIDE + kb];

    const uint4* wf4 = (const uint4*)g_wfrag;
    int pbase = wn * 256 + lane;   // uint4 index base within a chunk's 512

    uint32_t sa0 = smem_u32(sA);
    uint32_t sbB = smem_u32(sB);
    uint32_t bDst = sbB + tid * 16;
    const uint32_t bStageBytes = 512 * 16;

    int mR = lane >> 3, rr = lane & 7;
    uint32_t offA[2];
#pragma unroll
    for (int mi = 0; mi < 2; mi++)
        offA[mi] = (((wm * 32 + mi * 16 + (mR & 1) * 8 + rr) * ASTRIDE + (mR >> 1) * 4) << 2);

    float acc[2][8][4];
#pragma unroll
    for (int mi = 0; mi < 2; mi++)
#pragma unroll
        for (int ni = 0; ni < 8; ni++)
#pragma unroll
            for (int c = 0; c < 4; c++) acc[mi][ni][c] = 0.f;

    float pa[8];
    __syncthreads();   // tables ready

    // prologue: B chunk0 via cp.async; A chunk0 via regs -> stage 0
    cp_async16(bDst, wf4 + tid);
    cp_async16(bDst + 4096, wf4 + tid + 256);
    asm volatile("cp.async.commit_group;" ::: "memory");
#pragma unroll
    for (int i = 0; i < 8; i++) pa[i] = valid ? base[skoff[kb + i]] : 0.f;
    *(float4*)(aSm)     = make_float4(pa[0], pa[1], pa[2], pa[3]);
    *(float4*)(aSm + 4) = make_float4(pa[4], pa[5], pa[6], pa[7]);

    for (int ch = 0; ch < NCHUNK; ch++) {
        asm volatile("cp.async.wait_group 0;" ::: "memory");
        __syncthreads();   // A(ch)+B(ch) visible; stage (ch+1)&1 free

        if (ch + 1 < NCHUNK) {
            uint32_t bd = bDst + ((ch + 1) & 1) * bStageBytes;
            const uint4* ws = wf4 + (ch + 1) * 512 + tid;
            cp_async16(bd, ws);
            cp_async16(bd + 4096, ws + 256);
            asm volatile("cp.async.commit_group;" ::: "memory");
            int kg0 = (ch + 1) * KC;
#pragma unroll
            for (int i = 0; i < 8; i++) pa[i] = valid ? base[skoff[kg0 + kb + i]] : 0.f;
        }

        uint32_t stA = (ch & 1) * (BUFF << 2);
        const uint4* sBc = sB[ch & 1];
#pragma unroll
        for (int ks = 0; ks < 2; ks++) {
            uint32_t a[2][4];
            uint4 q[4];
#pragma unroll
            for (int pr = 0; pr < 4; pr++) q[pr] = sBc[pbase + pr * 64 + ks * 32];
#pragma unroll
            for (int mi = 0; mi < 2; mi++) ldsm_x4(a[mi], sa0 + offA[mi] + stA + ks * 32);
#pragma unroll
            for (int mi = 0; mi < 2; mi++)
#pragma unroll
                for (int pr = 0; pr < 4; pr++) {
                    mma_tf32(acc[mi][pr * 2 + 0], a[mi], (const uint32_t*)&q[pr]);
                    mma_tf32(acc[mi][pr * 2 + 1], a[mi], ((const uint32_t*)&q[pr]) + 2);
                }
        }

        if (ch + 1 < NCHUNK) {
            float* dA = aSm + ((ch + 1) & 1) * BUFF;
            *(float4*)(dA)     = make_float4(pa[0], pa[1], pa[2], pa[3]);
            *(float4*)(dA + 4) = make_float4(pa[4], pa[5], pa[6], pa[7]);
        }
    }
    __syncthreads();   // all MMAs done before epilogue overlays sA

    // ---------------- epilogue: raw region max, 4 column passes ----------------
    float* sm = &sA[0][0];   // overlay [128][33] = 4224 <= 2*BUFF = 5120
    for (int q = 0; q < 4; q++) {
        if ((q >> 1) == wn) {
            int ni0 = (q & 1) * 4;
#pragma unroll
            for (int mi = 0; mi < 2; mi++) {
#pragma unroll
                for (int nj = 0; nj < 4; nj++) {
                    int ni = ni0 + nj;
                    int colg = wn * 64 + ni * 8 + 2 * tg;
                    int colp = (colg - q * 32);
                    int r0 = wm * 32 + mi * 16 + gq;
#pragma unroll
                    for (int cc = 0; cc < 2; cc++) {
                        sm[r0 * 33 + colp + cc] = acc[mi][ni][cc];
                        sm[(r0 + 8) * 33 + colp + cc] = acc[mi][ni][2 + cc];
                    }
                }
            }
        }
        __syncthreads();
        if (tid < 128) {
            int ccol = tid & 31;
            int myreg = tid >> 5;
            float mx = -INFINITY;
            for (int row = 0; row < 128; row++) {
                float v = sm[row * 33 + ccol];
                mx = (srowreg[row] == (unsigned char)myreg) ? fmaxf(mx, v) : mx;
            }
            g_partial[((img * MT + mt) * 4 + myreg) * 128 + q * 32 + ccol] = mx;
        }
        __syncthreads();
    }
}

// ---------------- reduce partials; apply 1/sigma, bias, leaky ----------------
__global__ void vis_reduce_kernel(const float* __restrict__ cb) {
    int img = blockIdx.x;
    int o = threadIdx.x;    // 512
    int r = o >> 7;
    int col = o & 127;
    float m = -INFINITY;
    for (int mt = 0; mt < MT; mt++)
        m = fmaxf(m, g_partial[((img * MT + mt) * 4 + r) * 128 + col]);
    float v = m * inv_sigma_from(0) + cb[col];
    v = (v >= 0.f) ? v : 0.2f * v;
    g_pool_vis[img * 512 + col * 4 + r] = v;
}

// ---------------- vis score ----------------
__global__ void vis_score_kernel(const float* __restrict__ fcvb, float* __restrict__ out) {
    __shared__ float xs[512];
    int b = blockIdx.x, tid = threadIdx.x;
    for (int i = tid; i < 512; i += 256) xs[i] = g_pool_vis[b * 512 + i];
    __syncthreads();
    float acc = fcvb[tid];
    for (int j = 0; j < 512; j++) acc += xs[j] * g_fcvT[j * OUTD + tid];
    out[b * OUTD + tid] = acc;
}

// ---------------- topo score ----------------
__global__ void topo_score_kernel(const float* __restrict__ fctb, float* __restrict__ out) {
    __shared__ float xs[128];
    int b = blockIdx.x, tid = threadIdx.x;
    if (tid < 128) {
        float m = g_topo_part[(b * 4 + 0) * 128 + tid];
        m = fmaxf(m, g_topo_part[(b * 4 + 1) * 128 + tid]);
        m = fmaxf(m, g_topo_part[(b * 4 + 2) * 128 + tid]);
        m = fmaxf(m, g_topo_part[(b * 4 + 3) * 128 + tid]);
        xs[tid] = m;
    }
    __syncthreads();
    float acc = fctb[tid];
    for (int j = 0; j < 128; j++) acc += xs[j] * g_fctT[j * OUTD + tid];
    out[BBATCH * OUTD + b * OUTD + tid] = acc;
}

// ---------------- launch: fork/join overlap (s0 = conv, s1 = everything else) -----
extern "C" void kernel_launch(void* const* d_in, const int* in_sizes, int n_in,
                              void* d_out, int out_size) {
    const float* vis    = (const float*)d_in[0];
    const float* topo   = (const float*)d_in[1];
    const int*   ei     = (const int*)d_in[2];
    const int*   batch  = (const int*)d_in[3];
    const float* conv_w = (const float*)d_in[4];
    const float* conv_b = (const float*)d_in[5];
    const float* conv_u = (const float*)d_in[6];
    const float* fcv_w  = (const float*)d_in[7];
    const float* fcv_b  = (const float*)d_in[8];
    const float* fcv_u  = (const float*)d_in[9];
    const float* gcn_w  = (const float*)d_in[10];
    const float* gcn_b  = (const float*)d_in[11];
    const float* fct_w  = (const float*)d_in[12];
    const float* fct_b  = (const float*)d_in[13];
    const float* fct_u  = (const float*)d_in[14];
    float*       out    = (float*)d_out;

    cudaStream_t s1;
    cudaStreamCreateWithFlags(&s1, cudaStreamNonBlocking);
    cudaEvent_t evFork, evJoin;
    cudaEventCreateWithFlags(&evFork, cudaEventDisableTiming);
    cudaEventCreateWithFlags(&evJoin, cudaEventDisableTiming);

    // s0: prep (zeroes g_h/g_deg/g_acc) -> fork
    prep_kernel<<<(NN * DD + 255) / 256, 256>>>();
    cudaEventRecord(evFork, 0);
    cudaStreamWaitEvent(s1, evFork, 0);

    // s0: conv path (dominant)
    wfrag_kernel<<<(KTOT * DD + 255) / 256, 256>>>(conv_w);
    conv_mma_kernel<<<BBATCH * MT, 256>>>(vis);

    // s1: everything independent of conv
    sigma_v<<<(1152 + 255) / 256, 256, 0, s1>>>(conv_w, conv_u, 128, 1152, 0);
    sigma_t<<<(128 + 7) / 8, 256, 0, s1>>>(conv_w, 128, 1152, 0);
    deg_kernel<<<(NE + 255) / 256, 256, 0, s1>>>(ei);
    dis_kernel<<<(NN + 255) / 256, 256, 0, s1>>>();
    xw_kernel<<<NN / 8, 128, 0, s1>>>(topo, gcn_w);
    scatter_kernel<<<NE / 8, 256, 0, s1>>>(ei);
    {
        dim3 g(BBATCH, 4);
        topo_pool_kernel<<<g, 128, 0, s1>>>(batch, gcn_b);
    }
    sigma_v<<<(512 + 255) / 256, 256, 0, s1>>>(fcv_w, fcv_u, 256, 512, 1);
    sigma_t<<<(256 + 7) / 8, 256, 0, s1>>>(fcv_w, 256, 512, 1);
    sigma_v<<<(128 + 255) / 256, 256, 0, s1>>>(fct_w, fct_u, 256, 128, 2);
    sigma_t<<<(256 + 7) / 8, 256, 0, s1>>>(fct_w, 256, 128, 2);
    transpose_fcv<<<(256 * 512 + 255) / 256, 256, 0, s1>>>(fcv_w);
    transpose_fct<<<(256 * 128 + 255) / 256, 256, 0, s1>>>(fct_w);
    cudaEventRecord(evJoin, s1);

    // join on s0, then epilogue chain
    cudaStreamWaitEvent(0, evJoin, 0);
    vis_reduce_kernel<<<BBATCH, 512>>>(conv_b);
    vis_score_kernel<<<BBATCH, 256>>>(fcv_b, out);
    topo_score_kernel<<<BBATCH, 256>>>(fct_b, out);

    cudaEventDestroy(evFork);
    cudaEventDestroy(evJoin);
    cudaStreamDestroy(s1);
}

// round 16
// speedup vs baseline: 1.1895x; 1.0756x over previous
#include <cuda_runtime.h>
#include <cuda_fp16.h>
#include <math.h>
#include <stdint.h>

#define NN 20000
#define NE 640000
#define DD 128
#define OUTD 256
#define BBATCH 64
#define HOUT 62
#define MPI (HOUT*HOUT)   // 3844 pixels per image
#define MT 31             // M-tiles of 128 per image
#define KTOT 1152
#define KC 16             // K chunk = one k16 MMA step
#define NCHUNK (KTOT/KC)  // 72
#define ASTRB 48          // A row stride in bytes (24 halves): 16B-aligned, conflict-free
#define ABYTES (128*ASTRB) // 6144 bytes per A stage

// ---------------- scratch ----------------
__device__ __align__(16) float    g_acc[8];              // [slot]{ ||v||^2, ||Wv||^2 }
__device__ __align__(16) float    g_sv[3 * 1152];        // v = W^T u per slot
__device__ __align__(16) uint32_t g_wfragh[NCHUNK * 1024]; // fp16 B fragments [ch][ng][lane][2]
__device__ __align__(16) float    g_fcvT[512 * OUTD];
__device__ __align__(16) float    g_fctT[DD * OUTD];
__device__ __align__(16) float    g_partial[BBATCH * MT * 4 * DD];
__device__ __align__(16) float    g_pool_vis[BBATCH * DD * 4];
__device__ __align__(16) float    g_topo_part[BBATCH * 4 * DD];
__device__ __align__(16) float    g_deg[NN];
__device__ __align__(16) float    g_dis[NN];
__device__ __align__(16) float    g_xw[NN * DD];
__device__ __align__(16) float    g_h[NN * DD];

__device__ __forceinline__ int clampi(int v, int lo, int hi) {
    return v < lo ? lo : (v > hi ? hi : v);
}
__device__ __forceinline__ uint32_t smem_u32(const void* p) {
    uint32_t a;
    asm("{ .reg .u64 t; cvta.to.shared.u64 t, %1; cvt.u32.u64 %0, t; }" : "=r"(a) : "l"(p));
    return a;
}
__device__ __forceinline__ void mma_f16(float* d, const uint32_t* a, const uint32_t* b) {
    asm volatile(
        "mma.sync.aligned.m16n8k16.row.col.f32.f16.f16.f32 "
        "{%0,%1,%2,%3}, {%4,%5,%6,%7}, {%8,%9}, {%0,%1,%2,%3};"
        : "+f"(d[0]), "+f"(d[1]), "+f"(d[2]), "+f"(d[3])
        : "r"(a[0]), "r"(a[1]), "r"(a[2]), "r"(a[3]), "r"(b[0]), "r"(b[1]));
}
__device__ __forceinline__ void ldsm_x4(uint32_t* r, uint32_t addr) {
    asm volatile("ldmatrix.sync.aligned.m8n8.x4.shared.b16 {%0,%1,%2,%3}, [%4];"
                 : "=r"(r[0]), "=r"(r[1]), "=r"(r[2]), "=r"(r[3]) : "r"(addr));
}
__device__ __forceinline__ void cp_async16(uint32_t dst, const void* src) {
    asm volatile("cp.async.cg.shared.global [%0], [%1], 16;"
                 :: "r"(dst), "l"(src) : "memory");
}
__device__ __forceinline__ uint32_t pack_h2(float a, float b) {
    __half2 h = __floats2half2_rn(a, b);
    return *(uint32_t*)&h;
}
// sigma = s^2/(s+eps) with s = ||Wv||/(||v||+eps); returns 1/sigma
__device__ __forceinline__ float inv_sigma_from(int slot) {
    float vn = sqrtf(g_acc[slot * 2 + 0]);
    float tn = sqrtf(g_acc[slot * 2 + 1]);
    float s = tn / (vn + 1e-12f);
    float sigma = s * s / (s + 1e-12f);
    return 1.0f / sigma;
}

// ---------------- prep: zero scratch ----------------
__global__ void prep_kernel() {
    int idx = blockIdx.x * 256 + threadIdx.x;
    if (idx < NN * DD) g_h[idx] = 0.f;
    if (idx < NN) g_deg[idx] = 1.0f;     // self loop
    if (idx < 8) g_acc[idx] = 0.f;
}

// ---------------- spectral norm: v = W^T u (coalesced), ||v||^2 ----------------
__global__ void sigma_v(const float* __restrict__ W, const float* __restrict__ u,
                        int R, int C, int slot) {
    int j = blockIdx.x * 256 + threadIdx.x;
    if (j >= C) return;
    float t = 0.f;
    for (int i = 0; i < R; i++) t += W[i * C + j] * u[i];
    g_sv[slot * 1152 + j] = t;
    atomicAdd(&g_acc[slot * 2 + 0], t * t);
}

// ---------------- spectral norm: ||W v||^2, warp per row ----------------
__global__ void sigma_t(const float* __restrict__ W, int R, int C, int slot) {
    int warp = threadIdx.x >> 5, lane = threadIdx.x & 31;
    int i = blockIdx.x * 8 + warp;
    if (i >= R) return;
    const float* sv = &g_sv[slot * 1152];
    float t = 0.f;
    for (int j = lane; j < C; j += 32) t += W[i * C + j] * sv[j];
#pragma unroll
    for (int o = 16; o > 0; o >>= 1) t += __shfl_xor_sync(0xFFFFFFFFu, t, o);
    if (lane == 0) atomicAdd(&g_acc[slot * 2 + 1], t * t);
}

// ---------------- conv weights -> fp16 B fragments (m16n8k16 .col) ----------------
// idx = ch*1024 + ng*64 + lane*2 + reg; half2 = (W[n][k0], W[n][k0+1])
// n = ng*8 + lane/4, k0 = ch*16 + reg*8 + 2*(lane&3)
__global__ void wfrag_kernel(const float* __restrict__ src) {
    int idx = blockIdx.x * 256 + threadIdx.x;
    if (idx >= NCHUNK * 1024) return;
    int reg = idx & 1;
    int lane = (idx >> 1) & 31;
    int ng = (idx >> 6) & 15;
    int ch = idx >> 10;
    int n = ng * 8 + (lane >> 2);
    int k0 = ch * 16 + reg * 8 + 2 * (lane & 3);
    g_wfragh[idx] = pack_h2(src[n * KTOT + k0], src[n * KTOT + k0 + 1]);
}

// ---------------- fc weight transpose + scale (inline sigma) ----------------
__global__ void transpose_fcv(const float* __restrict__ src) {
    int idx = blockIdx.x * 256 + threadIdx.x;
    if (idx >= 256 * 512) return;
    int r = idx / 512, c = idx - r * 512;
    g_fcvT[c * 256 + r] = src[idx] * inv_sigma_from(1);
}
__global__ void transpose_fct(const float* __restrict__ src) {
    int idx = blockIdx.x * 256 + threadIdx.x;
    if (idx >= 256 * 128) return;
    int r = idx / 128, c = idx - r * 128;
    g_fctT[c * 256 + r] = src[idx] * inv_sigma_from(2);
}

// ---------------- degree + normalization ----------------
__global__ void deg_kernel(const int* __restrict__ ei) {
    int e = blockIdx.x * 256 + threadIdx.x;
    if (e < NE) atomicAdd(&g_deg[clampi(ei[NE + e], 0, NN - 1)], 1.0f);
}
__global__ void dis_kernel() {
    int i = blockIdx.x * 256 + threadIdx.x;
    if (i < NN) g_dis[i] = rsqrtf(g_deg[i]);
}

// ---------------- xw = topo @ gcn_w ----------------
__global__ void xw_kernel(const float* __restrict__ topo, const float* __restrict__ gw) {
    __shared__ float st[8 * 128];
    int n0 = blockIdx.x * 8;
    int tid = threadIdx.x;
#pragma unroll
    for (int i = 0; i < 8; i++) st[i * 128 + tid] = topo[(n0 + i) * 128 + tid];
    __syncthreads();
    float acc[8];
#pragma unroll
    for (int r = 0; r < 8; r++) acc[r] = 0.f;
    for (int k = 0; k < 128; k++) {
        float w = gw[k * 128 + tid];
#pragma unroll
        for (int r = 0; r < 8; r++) acc[r] += st[r * 128 + k] * w;
    }
#pragma unroll
    for (int r = 0; r < 8; r++) g_xw[(n0 + r) * 128 + tid] = acc[r];
}

// ---------------- edge scatter via red.v4 ----------------
__global__ void scatter_kernel(const int* __restrict__ ei) {
    int e = blockIdx.x * 8 + (threadIdx.x >> 5);
    if (e >= NE) return;
    int lane = threadIdx.x & 31;
    int src = clampi(ei[e], 0, NN - 1);
    int dst = clampi(ei[NE + e], 0, NN - 1);
    float nrm = g_dis[src] * g_dis[dst];
    float4 v = *(const float4*)&g_xw[src * 128 + lane * 4];
    asm volatile("red.global.add.v4.f32 [%0], {%1, %2, %3, %4};"
                 :: "l"(&g_h[dst * 128 + lane * 4]),
                    "f"(v.x * nrm), "f"(v.y * nrm), "f"(v.z * nrm), "f"(v.w * nrm)
                 : "memory");
}

// ---------------- topo pool ----------------
__global__ void topo_pool_kernel(const int* __restrict__ batch, const float* __restrict__ gb) {
    int b = blockIdx.x;
    int stripe = blockIdx.y;
    int c = threadIdx.x;

    int lo = 0, hi = NN;
    while (lo < hi) { int mid = (lo + hi) >> 1; if (batch[mid] < b) lo = mid + 1; else hi = mid; }
    int s = lo;
    lo = s; hi = NN;
    while (lo < hi) { int mid = (lo + hi) >> 1; if (batch[mid] < b + 1) lo = mid + 1; else hi = mid; }
    int e = lo;

    float bias = gb[c];
    float m = -INFINITY;
    for (int n = s + stripe; n < e; n += 4) {
        float d = g_dis[n];
        float val = g_h[n * 128 + c] + d * d * g_xw[n * 128 + c] + bias;
        val = (val >= 0.f) ? val : 0.2f * val;
        m = fmaxf(m, val);
    }
    g_topo_part[(b * 4 + stripe) * 128 + c] = m;
}

// ---------------- conv3x3: fp16 m16n8k16 mma; A fp16 staged, B cp.async frag ------
// block 128 pixels x 128 cout; 8 warps 4x2 (warp tile 32x64)
__global__ void __launch_bounds__(256, 2)
conv_mma_kernel(const float* __restrict__ vis) {
    __shared__ __align__(16) unsigned char sAr[2][ABYTES];  // 12KB total
    __shared__ __align__(16) uint4 sB[2][256];              // 8KB  (fp16 frags, linear)
    __shared__ int skoff[KTOT];
    __shared__ unsigned char srowreg[128];

    int tid = threadIdx.x;
    int warp = tid >> 5, lane = tid & 31;
    int wm = warp & 3;        // rows 32*wm
    int wn = warp >> 2;       // cols 64*wn
    int gq = lane >> 2, tg = lane & 3;

    int img = blockIdx.x / MT;
    int mt = blockIdx.x - img * MT;
    int m0 = mt * 128;

    for (int k = tid; k < KTOT; k += 256) {
        int ci = k / 9, rem = k - ci * 9, ky = rem / 3, kx = rem - ky * 3;
        skoff[k] = ci * 4096 + ky * 64 + kx;
    }
    if (tid < 128) {
        int s = m0 + tid;
        unsigned char r = 4;
        if (s < MPI) {
            int yy = s / HOUT, xx = s - yy * HOUT;
            r = (unsigned char)(((yy >= 31) ? 2 : 0) + ((xx >= 31) ? 1 : 0));
        }
        srowreg[tid] = r;
    }

    // A gather: pixel p = tid&127, k sub-range kb..kb+7 (kb = (tid>>7)*8)
    int p = tid & 127;
    int kbo = (tid >> 7) * 16;     // byte offset within row (8 halves = 16B)
    int kb = (tid >> 7) * 8;
    int s = m0 + p;
    bool valid = (s < MPI);
    int y = valid ? (s / HOUT) : 0;
    int x = valid ? (s - y * HOUT) : 0;
    const float* base = vis + (size_t)img * 128 * 4096 + y * 64 + x;
    unsigned char* aSm = &sAr[0][p * ASTRB + kbo];

    const uint4* wf4 = (const uint4*)g_wfragh;   // 256 uint4 per chunk

    uint32_t sa0 = smem_u32(sAr);
    uint32_t sbB = smem_u32(sB);
    uint32_t bDst = sbB + tid * 16;
    const uint32_t bStageBytes = 256 * 16;

    int mR = lane >> 3, rr = lane & 7;
    uint32_t offA[2];
#pragma unroll
    for (int mi = 0; mi < 2; mi++)
        offA[mi] = (uint32_t)((wm * 32 + mi * 16 + (mR & 1) * 8 + rr) * ASTRB + (mR >> 1) * 16);

    float acc[2][8][4];
#pragma unroll
    for (int mi = 0; mi < 2; mi++)
#pragma unroll
        for (int ni = 0; ni < 8; ni++)
#pragma unroll
            for (int c = 0; c < 4; c++) acc[mi][ni][c] = 0.f;

    float pa[8];
    __syncthreads();   // tables ready

    // prologue: B chunk0 via cp.async (1x16B/thread); A chunk0 regs -> fp16 -> stage 0
    cp_async16(bDst, wf4 + tid);
    asm volatile("cp.async.commit_group;" ::: "memory");
#pragma unroll
    for (int i = 0; i < 8; i++) pa[i] = valid ? base[skoff[kb + i]] : 0.f;
    {
        uint4 h;
        h.x = pack_h2(pa[0], pa[1]); h.y = pack_h2(pa[2], pa[3]);
        h.z = pack_h2(pa[4], pa[5]); h.w = pack_h2(pa[6], pa[7]);
        *(uint4*)aSm = h;
    }

    for (int ch = 0; ch < NCHUNK; ch++) {
        asm volatile("cp.async.wait_group 0;" ::: "memory");
        __syncthreads();   // A(ch)+B(ch) visible; stage (ch+1)&1 free

        if (ch + 1 < NCHUNK) {
            uint32_t bd = bDst + ((ch + 1) & 1) * bStageBytes;
            cp_async16(bd, wf4 + (ch + 1) * 256 + tid);
            asm volatile("cp.async.commit_group;" ::: "memory");
            int kg0 = (ch + 1) * KC;
#pragma unroll
            for (int i = 0; i < 8; i++) pa[i] = valid ? base[skoff[kg0 + kb + i]] : 0.f;
        }

        uint32_t stA = (ch & 1) * ABYTES;
        const uint2* sBc = (const uint2*)sB[ch & 1];
        {
            uint32_t a[2][4];
            uint2 b[8];
#pragma unroll
            for (int pr = 0; pr < 8; pr++) b[pr] = sBc[(wn * 8 + pr) * 32 + lane];
#pragma unroll
            for (int mi = 0; mi < 2; mi++) ldsm_x4(a[mi], sa0 + offA[mi] + stA);
#pragma unroll
            for (int mi = 0; mi < 2; mi++)
#pragma unroll
                for (int pr = 0; pr < 8; pr++)
                    mma_f16(acc[mi][pr], a[mi], (const uint32_t*)&b[pr]);
        }

        if (ch + 1 < NCHUNK) {
            unsigned char* dA = aSm + ((ch + 1) & 1) * ABYTES;
            uint4 h;
            h.x = pack_h2(pa[0], pa[1]); h.y = pack_h2(pa[2], pa[3]);
            h.z = pack_h2(pa[4], pa[5]); h.w = pack_h2(pa[6], pa[7]);
            *(uint4*)dA = h;
        }
    }
    __syncthreads();   // all MMAs done before epilogue overlays sAr

    // ---------------- epilogue: raw region max, 4 column passes ----------------
    float* sm = (float*)&sAr[0][0];   // overlay [128][33] floats = 16896B <= 2*ABYTES+... (12288) NO
    // overlay needs 16896 bytes; sAr(12288)+sB(8192) are contiguous? Not guaranteed.
    // Use a 2-pass scheme in sAr only: [128][24] floats = 12288 bytes exactly.
    // 24 cols per pass, 6 passes? Simpler: [128][24] with 16-col passes (stride 24, no conflicts at 16/24 mix).
    // We do 8 passes of 16 columns: buffer [128][17] floats = 8704B <= 12288.
    for (int q = 0; q < 8; q++) {
        int qw = q >> 2;           // which wn owns this 16-col group
        if (qw == wn) {
            int ni0 = (q & 3) * 2; // two n8 tiles per pass
#pragma unroll
            for (int mi = 0; mi < 2; mi++) {
#pragma unroll
                for (int nj = 0; nj < 2; nj++) {
                    int ni = ni0 + nj;
                    int colg = wn * 64 + ni * 8 + 2 * tg;
                    int colp = colg - q * 16;
                    int r0 = wm * 32 + mi * 16 + gq;
#pragma unroll
                    for (int cc = 0; cc < 2; cc++) {
                        sm[r0 * 17 + colp + cc] = acc[mi][ni][cc];
                        sm[(r0 + 8) * 17 + colp + cc] = acc[mi][ni][2 + cc];
                    }
                }
            }
        }
        __syncthreads();
        if (tid < 64) {
            int ccol = tid & 15;
            int myreg = tid >> 4;
            float mx = -INFINITY;
            for (int row = 0; row < 128; row++) {
                float v = sm[row * 17 + ccol];
                mx = (srowreg[row] == (unsigned char)myreg) ? fmaxf(mx, v) : mx;
            }
            g_partial[((img * MT + mt) * 4 + myreg) * 128 + q * 16 + ccol] = mx;
        }
        __syncthreads();
    }
}

// ---------------- reduce partials; apply 1/sigma, bias, leaky ----------------
__global__ void vis_reduce_kernel(const float* __restrict__ cb) {
    int img = blockIdx.x;
    int o = threadIdx.x;    // 512
    int r = o >> 7;
    int col = o & 127;
    float m = -INFINITY;
    for (int mt = 0; mt < MT; mt++)
        m = fmaxf(m, g_partial[((img * MT + mt) * 4 + r) * 128 + col]);
    float v = m * inv_sigma_from(0) + cb[col];
    v = (v >= 0.f) ? v : 0.2f * v;
    g_pool_vis[img * 512 + col * 4 + r] = v;
}

// ---------------- vis score ----------------
__global__ void vis_score_kernel(const float* __restrict__ fcvb, float* __restrict__ out) {
    __shared__ float xs[512];
    int b = blockIdx.x, tid = threadIdx.x;
    for (int i = tid; i < 512; i += 256) xs[i] = g_pool_vis[b * 512 + i];
    __syncthreads();
    float acc = fcvb[tid];
    for (int j = 0; j < 512; j++) acc += xs[j] * g_fcvT[j * OUTD + tid];
    out[b * OUTD + tid] = acc;
}

// ---------------- topo score ----------------
__global__ void topo_score_kernel(const float* __restrict__ fctb, float* __restrict__ out) {
    __shared__ float xs[128];
    int b = blockIdx.x, tid = threadIdx.x;
    if (tid < 128) {
        float m = g_topo_part[(b * 4 + 0) * 128 + tid];
        m = fmaxf(m, g_topo_part[(b * 4 + 1) * 128 + tid]);
        m = fmaxf(m, g_topo_part[(b * 4 + 2) * 128 + tid]);
        m = fmaxf(m, g_topo_part[(b * 4 + 3) * 128 + tid]);
        xs[tid] = m;
    }
    __syncthreads();
    float acc = fctb[tid];
    for (int j = 0; j < 128; j++) acc += xs[j] * g_fctT[j * OUTD + tid];
    out[BBATCH * OUTD + b * OUTD + tid] = acc;
}

// ---------------- launch: fork/join overlap (s0 = conv, s1 = everything else) -----
extern "C" void kernel_launch(void* const* d_in, const int* in_sizes, int n_in,
                              void* d_out, int out_size) {
    const float* vis    = (const float*)d_in[0];
    const float* topo   = (const float*)d_in[1];
    const int*   ei     = (const int*)d_in[2];
    const int*   batch  = (const int*)d_in[3];
    const float* conv_w = (const float*)d_in[4];
    const float* conv_b = (const float*)d_in[5];
    const float* conv_u = (const float*)d_in[6];
    const float* fcv_w  = (const float*)d_in[7];
    const float* fcv_b  = (const float*)d_in[8];
    const float* fcv_u  = (const float*)d_in[9];
    const float* gcn_w  = (const float*)d_in[10];
    const float* gcn_b  = (const float*)d_in[11];
    const float* fct_w  = (const float*)d_in[12];
    const float* fct_b  = (const float*)d_in[13];
    const float* fct_u  = (const float*)d_in[14];
    float*       out    = (float*)d_out;

    cudaStream_t s1;
    cudaStreamCreateWithFlags(&s1, cudaStreamNonBlocking);
    cudaEvent_t evFork, evJoin;
    cudaEventCreateWithFlags(&evFork, cudaEventDisableTiming);
    cudaEventCreateWithFlags(&evJoin, cudaEventDisableTiming);

    // s0: prep (zeroes g_h/g_deg/g_acc) -> fork
    prep_kernel<<<(NN * DD + 255) / 256, 256>>>();
    cudaEventRecord(evFork, 0);
    cudaStreamWaitEvent(s1, evFork, 0);

    // s0: conv path (dominant)
    wfrag_kernel<<<(NCHUNK * 1024 + 255) / 256, 256>>>(conv_w);
    conv_mma_kernel<<<BBATCH * MT, 256>>>(vis);

    // s1: everything independent of conv
    sigma_v<<<(1152 + 255) / 256, 256, 0, s1>>>(conv_w, conv_u, 128, 1152, 0);
    sigma_t<<<(128 + 7) / 8, 256, 0, s1>>>(conv_w, 128, 1152, 0);
    deg_kernel<<<(NE + 255) / 256, 256, 0, s1>>>(ei);
    dis_kernel<<<(NN + 255) / 256, 256, 0, s1>>>();
    xw_kernel<<<NN / 8, 128, 0, s1>>>(topo, gcn_w);
    scatter_kernel<<<NE / 8, 256, 0, s1>>>(ei);
    {
        dim3 g(BBATCH, 4);
        topo_pool_kernel<<<g, 128, 0, s1>>>(batch, gcn_b);
    }
    sigma_v<<<(512 + 255) / 256, 256, 0, s1>>>(fcv_w, fcv_u, 256, 512, 1);
    sigma_t<<<(256 + 7) / 8, 256, 0, s1>>>(fcv_w, 256, 512, 1);
    sigma_v<<<(128 + 255) / 256, 256, 0, s1>>>(fct_w, fct_u, 256, 128, 2);
    sigma_t<<<(256 + 7) / 8, 256, 0, s1>>>(fct_w, 256, 128, 2);
    transpose_fcv<<<(256 * 512 + 255) / 256, 256, 0, s1>>>(fcv_w);
    transpose_fct<<<(256 * 128 + 255) / 256, 256, 0, s1>>>(fct_w);
    cudaEventRecord(evJoin, s1);

    // join on s0, then epilogue chain
    cudaStreamWaitEvent(0, evJoin, 0);
    vis_reduce_kernel<<<BBATCH, 512>>>(conv_b);
    vis_score_kernel<<<BBATCH, 256>>>(fcv_b, out);
    topo_score_kernel<<<BBATCH, 256>>>(fct_b, out);

    cudaEventDestroy(evFork);
    cudaEventDestroy(evJoin);
    cudaStreamDestroy(s1);
}

// round 17
// speedup vs baseline: 1.2947x; 1.0885x over previous
#include <cuda_runtime.h>
#include <cuda_fp16.h>
#include <math.h>
#include <stdint.h>

#define NN 20000
#define NE 640000
#define DD 128
#define OUTD 256
#define BBATCH 64
#define HOUT 62
#define MPI (HOUT*HOUT)   // 3844 pixels per image
#define MT 31             // M-tiles of 128 per image
#define KTOT 1152
#define KC 32             // K chunk = two k16 MMA steps
#define NCHUNK (KTOT/KC)  // 36
#define ASTRB 80          // A row stride in bytes (32 halves + 16B pad): conflict-free
#define ABYTES (128*ASTRB) // 10240 bytes per A stage

// ---------------- scratch ----------------
__device__ __align__(16) float    g_acc[8];              // [slot]{ ||v||^2, ||Wv||^2 }
__device__ __align__(16) float    g_sv[3 * 1152];        // v = W^T u per slot
__device__ __align__(16) uint32_t g_wfragh[72 * 1024];   // fp16 B fragments per k16 [72][1024]
__device__ __align__(16) float    g_fcvT[512 * OUTD];
__device__ __align__(16) float    g_fctT[DD * OUTD];
__device__ __align__(16) float    g_partial[BBATCH * MT * 4 * DD];
__device__ __align__(16) float    g_pool_vis[BBATCH * DD * 4];
__device__ __align__(16) float    g_topo_part[BBATCH * 4 * DD];
__device__ __align__(16) float    g_deg[NN];
__device__ __align__(16) float    g_dis[NN];
__device__ __align__(16) float    g_xw[NN * DD];
__device__ __align__(16) float    g_h[NN * DD];

__device__ __forceinline__ int clampi(int v, int lo, int hi) {
    return v < lo ? lo : (v > hi ? hi : v);
}
__device__ __forceinline__ uint32_t smem_u32(const void* p) {
    uint32_t a;
    asm("{ .reg .u64 t; cvta.to.shared.u64 t, %1; cvt.u32.u64 %0, t; }" : "=r"(a) : "l"(p));
    return a;
}
__device__ __forceinline__ void mma_f16(float* d, const uint32_t* a, const uint32_t* b) {
    asm volatile(
        "mma.sync.aligned.m16n8k16.row.col.f32.f16.f16.f32 "
        "{%0,%1,%2,%3}, {%4,%5,%6,%7}, {%8,%9}, {%0,%1,%2,%3};"
        : "+f"(d[0]), "+f"(d[1]), "+f"(d[2]), "+f"(d[3])
        : "r"(a[0]), "r"(a[1]), "r"(a[2]), "r"(a[3]), "r"(b[0]), "r"(b[1]));
}
__device__ __forceinline__ void ldsm_x4(uint32_t* r, uint32_t addr) {
    asm volatile("ldmatrix.sync.aligned.m8n8.x4.shared.b16 {%0,%1,%2,%3}, [%4];"
                 : "=r"(r[0]), "=r"(r[1]), "=r"(r[2]), "=r"(r[3]) : "r"(addr));
}
__device__ __forceinline__ void cp_async16(uint32_t dst, const void* src) {
    asm volatile("cp.async.cg.shared.global [%0], [%1], 16;"
                 :: "r"(dst), "l"(src) : "memory");
}
__device__ __forceinline__ uint32_t pack_h2(float a, float b) {
    __half2 h = __floats2half2_rn(a, b);
    return *(uint32_t*)&h;
}
// sigma = s^2/(s+eps) with s = ||Wv||/(||v||+eps); returns 1/sigma
__device__ __forceinline__ float inv_sigma_from(int slot) {
    float vn = sqrtf(g_acc[slot * 2 + 0]);
    float tn = sqrtf(g_acc[slot * 2 + 1]);
    float s = tn / (vn + 1e-12f);
    float sigma = s * s / (s + 1e-12f);
    return 1.0f / sigma;
}

// ---------------- prep: zero scratch ----------------
__global__ void prep_kernel() {
    int idx = blockIdx.x * 256 + threadIdx.x;
    if (idx < NN * DD) g_h[idx] = 0.f;
    if (idx < NN) g_deg[idx] = 1.0f;     // self loop
    if (idx < 8) g_acc[idx] = 0.f;
}

// ---------------- spectral norm: v = W^T u (coalesced), ||v||^2 ----------------
__global__ void sigma_v(const float* __restrict__ W, const float* __restrict__ u,
                        int R, int C, int slot) {
    int j = blockIdx.x * 256 + threadIdx.x;
    if (j >= C) return;
    float t = 0.f;
    for (int i = 0; i < R; i++) t += W[i * C + j] * u[i];
    g_sv[slot * 1152 + j] = t;
    atomicAdd(&g_acc[slot * 2 + 0], t * t);
}

// ---------------- spectral norm: ||W v||^2, warp per row ----------------
__global__ void sigma_t(const float* __restrict__ W, int R, int C, int slot) {
    int warp = threadIdx.x >> 5, lane = threadIdx.x & 31;
    int i = blockIdx.x * 8 + warp;
    if (i >= R) return;
    const float* sv = &g_sv[slot * 1152];
    float t = 0.f;
    for (int j = lane; j < C; j += 32) t += W[i * C + j] * sv[j];
#pragma unroll
    for (int o = 16; o > 0; o >>= 1) t += __shfl_xor_sync(0xFFFFFFFFu, t, o);
    if (lane == 0) atomicAdd(&g_acc[slot * 2 + 1], t * t);
}

// ---------------- conv weights -> fp16 B fragments (m16n8k16 .col) ----------------
// idx = c16*1024 + ng*64 + lane*2 + reg; half2 = (W[n][k0], W[n][k0+1])
// n = ng*8 + lane/4, k0 = c16*16 + reg*8 + 2*(lane&3)
__global__ void wfrag_kernel(const float* __restrict__ src) {
    int idx = blockIdx.x * 256 + threadIdx.x;
    if (idx >= 72 * 1024) return;
    int reg = idx & 1;
    int lane = (idx >> 1) & 31;
    int ng = (idx >> 6) & 15;
    int c16 = idx >> 10;
    int n = ng * 8 + (lane >> 2);
    int k0 = c16 * 16 + reg * 8 + 2 * (lane & 3);
    g_wfragh[idx] = pack_h2(src[n * KTOT + k0], src[n * KTOT + k0 + 1]);
}

// ---------------- fc weight transpose + scale (inline sigma) ----------------
__global__ void transpose_fcv(const float* __restrict__ src) {
    int idx = blockIdx.x * 256 + threadIdx.x;
    if (idx >= 256 * 512) return;
    int r = idx / 512, c = idx - r * 512;
    g_fcvT[c * 256 + r] = src[idx] * inv_sigma_from(1);
}
__global__ void transpose_fct(const float* __restrict__ src) {
    int idx = blockIdx.x * 256 + threadIdx.x;
    if (idx >= 256 * 128) return;
    int r = idx / 128, c = idx - r * 128;
    g_fctT[c * 256 + r] = src[idx] * inv_sigma_from(2);
}

// ---------------- degree + normalization ----------------
__global__ void deg_kernel(const int* __restrict__ ei) {
    int e = blockIdx.x * 256 + threadIdx.x;
    if (e < NE) atomicAdd(&g_deg[clampi(ei[NE + e], 0, NN - 1)], 1.0f);
}
__global__ void dis_kernel() {
    int i = blockIdx.x * 256 + threadIdx.x;
    if (i < NN) g_dis[i] = rsqrtf(g_deg[i]);
}

// ---------------- xw = topo @ gcn_w ----------------
__global__ void xw_kernel(const float* __restrict__ topo, const float* __restrict__ gw) {
    __shared__ float st[8 * 128];
    int n0 = blockIdx.x * 8;
    int tid = threadIdx.x;
#pragma unroll
    for (int i = 0; i < 8; i++) st[i * 128 + tid] = topo[(n0 + i) * 128 + tid];
    __syncthreads();
    float acc[8];
#pragma unroll
    for (int r = 0; r < 8; r++) acc[r] = 0.f;
    for (int k = 0; k < 128; k++) {
        float w = gw[k * 128 + tid];
#pragma unroll
        for (int r = 0; r < 8; r++) acc[r] += st[r * 128 + k] * w;
    }
#pragma unroll
    for (int r = 0; r < 8; r++) g_xw[(n0 + r) * 128 + tid] = acc[r];
}

// ---------------- edge scatter via red.v4 ----------------
__global__ void scatter_kernel(const int* __restrict__ ei) {
    int e = blockIdx.x * 8 + (threadIdx.x >> 5);
    if (e >= NE) return;
    int lane = threadIdx.x & 31;
    int src = clampi(ei[e], 0, NN - 1);
    int dst = clampi(ei[NE + e], 0, NN - 1);
    float nrm = g_dis[src] * g_dis[dst];
    float4 v = *(const float4*)&g_xw[src * 128 + lane * 4];
    asm volatile("red.global.add.v4.f32 [%0], {%1, %2, %3, %4};"
                 :: "l"(&g_h[dst * 128 + lane * 4]),
                    "f"(v.x * nrm), "f"(v.y * nrm), "f"(v.z * nrm), "f"(v.w * nrm)
                 : "memory");
}

// ---------------- topo pool ----------------
__global__ void topo_pool_kernel(const int* __restrict__ batch, const float* __restrict__ gb) {
    int b = blockIdx.x;
    int stripe = blockIdx.y;
    int c = threadIdx.x;

    int lo = 0, hi = NN;
    while (lo < hi) { int mid = (lo + hi) >> 1; if (batch[mid] < b) lo = mid + 1; else hi = mid; }
    int s = lo;
    lo = s; hi = NN;
    while (lo < hi) { int mid = (lo + hi) >> 1; if (batch[mid] < b + 1) lo = mid + 1; else hi = mid; }
    int e = lo;

    float bias = gb[c];
    float m = -INFINITY;
    for (int n = s + stripe; n < e; n += 4) {
        float d = g_dis[n];
        float val = g_h[n * 128 + c] + d * d * g_xw[n * 128 + c] + bias;
        val = (val >= 0.f) ? val : 0.2f * val;
        m = fmaxf(m, val);
    }
    g_topo_part[(b * 4 + stripe) * 128 + c] = m;
}

// ---------------- conv3x3: fp16 m16n8k16, KC=32 (2 k-steps/stage), double-buffered -
// block 128 pixels x 128 cout; 8 warps 4x2 (warp tile 32x64)
__global__ void __launch_bounds__(256, 2)
conv_mma_kernel(const float* __restrict__ vis) {
    __shared__ __align__(16) unsigned char sAr[2][ABYTES];  // 20KB
    __shared__ __align__(16) uint4 sB[2][512];              // 16KB (2 k16 frag sets)
    __shared__ int skoff[KTOT];
    __shared__ unsigned char srowreg[128];

    int tid = threadIdx.x;
    int warp = tid >> 5, lane = tid & 31;
    int wm = warp & 3;        // rows 32*wm
    int wn = warp >> 2;       // cols 64*wn
    int gq = lane >> 2, tg = lane & 3;

    int img = blockIdx.x / MT;
    int mt = blockIdx.x - img * MT;
    int m0 = mt * 128;

    for (int k = tid; k < KTOT; k += 256) {
        int ci = k / 9, rem = k - ci * 9, ky = rem / 3, kx = rem - ky * 3;
        skoff[k] = ci * 4096 + ky * 64 + kx;
    }
    if (tid < 128) {
        int s = m0 + tid;
        unsigned char r = 4;
        if (s < MPI) {
            int yy = s / HOUT, xx = s - yy * HOUT;
            r = (unsigned char)(((yy >= 31) ? 2 : 0) + ((xx >= 31) ? 1 : 0));
        }
        srowreg[tid] = r;
    }

    // A gather: pixel p = tid&127, k half kb = tid>>7 covers 16 k values
    int p = tid & 127;
    int kh = tid >> 7;             // 0/1
    int kb = kh * 16;              // k base within chunk
    int s = m0 + p;
    bool valid = (s < MPI);
    int y = valid ? (s / HOUT) : 0;
    int x = valid ? (s - y * HOUT) : 0;
    const float* base = vis + (size_t)img * 128 * 4096 + y * 64 + x;
    unsigned char* aSm = &sAr[0][p * ASTRB + kh * 32];   // 16 halves = 32 bytes

    const uint4* wf4 = (const uint4*)g_wfragh;   // 512 uint4 per KC=32 chunk

    uint32_t sa0 = smem_u32(sAr);
    uint32_t sbB = smem_u32(sB);
    uint32_t bDst = sbB + tid * 16;
    const uint32_t bStageBytes = 512 * 16;

    int mR = lane >> 3, rr = lane & 7;
    uint32_t offA[2];
#pragma unroll
    for (int mi = 0; mi < 2; mi++)
        offA[mi] = (uint32_t)((wm * 32 + mi * 16 + (mR & 1) * 8 + rr) * ASTRB + (mR >> 1) * 16);

    float acc[2][8][4];
#pragma unroll
    for (int mi = 0; mi < 2; mi++)
#pragma unroll
        for (int ni = 0; ni < 8; ni++)
#pragma unroll
            for (int c = 0; c < 4; c++) acc[mi][ni][c] = 0.f;

    uint32_t ph[8];
    __syncthreads();   // tables ready

    // prologue: B chunk0 (2x16B/thread); A chunk0 -> fp16 regs -> stage 0
    cp_async16(bDst, wf4 + tid);
    cp_async16(bDst + 4096, wf4 + tid + 256);
    asm volatile("cp.async.commit_group;" ::: "memory");
#pragma unroll
    for (int i = 0; i < 8; i++) {
        float f0 = valid ? base[skoff[kb + 2 * i]] : 0.f;
        float f1 = valid ? base[skoff[kb + 2 * i + 1]] : 0.f;
        ph[i] = pack_h2(f0, f1);
    }
    ((uint4*)aSm)[0] = make_uint4(ph[0], ph[1], ph[2], ph[3]);
    ((uint4*)aSm)[1] = make_uint4(ph[4], ph[5], ph[6], ph[7]);

    for (int ch = 0; ch < NCHUNK; ch++) {
        asm volatile("cp.async.wait_group 0;" ::: "memory");
        __syncthreads();   // A(ch)+B(ch) visible; stage (ch+1)&1 free

        if (ch + 1 < NCHUNK) {
            uint32_t bd = bDst + ((ch + 1) & 1) * bStageBytes;
            const uint4* ws = wf4 + (ch + 1) * 512 + tid;
            cp_async16(bd, ws);
            cp_async16(bd + 4096, ws + 256);
            asm volatile("cp.async.commit_group;" ::: "memory");
            int kg0 = (ch + 1) * KC + kb;
#pragma unroll
            for (int i = 0; i < 8; i++) {
                float f0 = valid ? base[skoff[kg0 + 2 * i]] : 0.f;
                float f1 = valid ? base[skoff[kg0 + 2 * i + 1]] : 0.f;
                ph[i] = pack_h2(f0, f1);
            }
        }

        uint32_t stA = (ch & 1) * ABYTES;
        const uint2* sBc = (const uint2*)sB[ch & 1];
#pragma unroll
        for (int ks = 0; ks < 2; ks++) {
            uint32_t a[2][4];
            uint2 b[8];
            const uint2* sk = sBc + ks * 512;
#pragma unroll
            for (int pr = 0; pr < 8; pr++) b[pr] = sk[(wn * 8 + pr) * 32 + lane];
#pragma unroll
            for (int mi = 0; mi < 2; mi++) ldsm_x4(a[mi], sa0 + offA[mi] + stA + ks * 32);
#pragma unroll
            for (int mi = 0; mi < 2; mi++)
#pragma unroll
                for (int pr = 0; pr < 8; pr++)
                    mma_f16(acc[mi][pr], a[mi], (const uint32_t*)&b[pr]);
        }

        if (ch + 1 < NCHUNK) {
            unsigned char* dA = aSm + ((ch + 1) & 1) * ABYTES;
            ((uint4*)dA)[0] = make_uint4(ph[0], ph[1], ph[2], ph[3]);
            ((uint4*)dA)[1] = make_uint4(ph[4], ph[5], ph[6], ph[7]);
        }
    }
    __syncthreads();   // all MMAs done before epilogue overlays sAr

    // ---------------- epilogue: raw region max, 8 passes of 16 cols ----------------
    float* sm = (float*)&sAr[0][0];   // overlay [128][17] floats = 8704B <= 20480
    for (int q = 0; q < 8; q++) {
        int qw = q >> 2;
        if (qw == wn) {
            int ni0 = (q & 3) * 2;
#pragma unroll
            for (int mi = 0; mi < 2; mi++) {
#pragma unroll
                for (int nj = 0; nj < 2; nj++) {
                    int ni = ni0 + nj;
                    int colg = wn * 64 + ni * 8 + 2 * tg;
                    int colp = colg - q * 16;
                    int r0 = wm * 32 + mi * 16 + gq;
#pragma unroll
                    for (int cc = 0; cc < 2; cc++) {
                        sm[r0 * 17 + colp + cc] = acc[mi][ni][cc];
                        sm[(r0 + 8) * 17 + colp + cc] = acc[mi][ni][2 + cc];
                    }
                }
            }
        }
        __syncthreads();
        if (tid < 64) {
            int ccol = tid & 15;
            int myreg = tid >> 4;
            float mx = -INFINITY;
            for (int row = 0; row < 128; row++) {
                float v = sm[row * 17 + ccol];
                mx = (srowreg[row] == (unsigned char)myreg) ? fmaxf(mx, v) : mx;
            }
            g_partial[((img * MT + mt) * 4 + myreg) * 128 + q * 16 + ccol] = mx;
        }
        __syncthreads();
    }
}

// ---------------- reduce partials; apply 1/sigma, bias, leaky ----------------
__global__ void vis_reduce_kernel(const float* __restrict__ cb) {
    int img = blockIdx.x;
    int o = threadIdx.x;    // 512
    int r = o >> 7;
    int col = o & 127;
    float m = -INFINITY;
    for (int mt = 0; mt < MT; mt++)
        m = fmaxf(m, g_partial[((img * MT + mt) * 4 + r) * 128 + col]);
    float v = m * inv_sigma_from(0) + cb[col];
    v = (v >= 0.f) ? v : 0.2f * v;
    g_pool_vis[img * 512 + col * 4 + r] = v;
}

// ---------------- vis score ----------------
__global__ void vis_score_kernel(const float* __restrict__ fcvb, float* __restrict__ out) {
    __shared__ float xs[512];
    int b = blockIdx.x, tid = threadIdx.x;
    for (int i = tid; i < 512; i += 256) xs[i] = g_pool_vis[b * 512 + i];
    __syncthreads();
    float acc = fcvb[tid];
    for (int j = 0; j < 512; j++) acc += xs[j] * g_fcvT[j * OUTD + tid];
    out[b * OUTD + tid] = acc;
}

// ---------------- topo score ----------------
__global__ void topo_score_kernel(const float* __restrict__ fctb, float* __restrict__ out) {
    __shared__ float xs[128];
    int b = blockIdx.x, tid = threadIdx.x;
    if (tid < 128) {
        float m = g_topo_part[(b * 4 + 0) * 128 + tid];
        m = fmaxf(m, g_topo_part[(b * 4 + 1) * 128 + tid]);
        m = fmaxf(m, g_topo_part[(b * 4 + 2) * 128 + tid]);
        m = fmaxf(m, g_topo_part[(b * 4 + 3) * 128 + tid]);
        xs[tid] = m;
    }
    __syncthreads();
    float acc = fctb[tid];
    for (int j = 0; j < 128; j++) acc += xs[j] * g_fctT[j * OUTD + tid];
    out[BBATCH * OUTD + b * OUTD + tid] = acc;
}

// ---------------- launch: fork/join overlap (s0 = conv, s1 = everything else) -----
extern "C" void kernel_launch(void* const* d_in, const int* in_sizes, int n_in,
                              void* d_out, int out_size) {
    const float* vis    = (const float*)d_in[0];
    const float* topo   = (const float*)d_in[1];
    const int*   ei     = (const int*)d_in[2];
    const int*   batch  = (const int*)d_in[3];
    const float* conv_w = (const float*)d_in[4];
    const float* conv_b = (const float*)d_in[5];
    const float* conv_u = (const float*)d_in[6];
    const float* fcv_w  = (const float*)d_in[7];
    const float* fcv_b  = (const float*)d_in[8];
    const float* fcv_u  = (const float*)d_in[9];
    const float* gcn_w  = (const float*)d_in[10];
    const float* gcn_b  = (const float*)d_in[11];
    const float* fct_w  = (const float*)d_in[12];
    const float* fct_b  = (const float*)d_in[13];
    const float* fct_u  = (const float*)d_in[14];
    float*       out    = (float*)d_out;

    cudaStream_t s1;
    cudaStreamCreateWithFlags(&s1, cudaStreamNonBlocking);
    cudaEvent_t evFork, evJoin;
    cudaEventCreateWithFlags(&evFork, cudaEventDisableTiming);
    cudaEventCreateWithFlags(&evJoin, cudaEventDisableTiming);

    // s0: prep (zeroes g_h/g_deg/g_acc) -> fork
    prep_kernel<<<(NN * DD + 255) / 256, 256>>>();
    cudaEventRecord(evFork, 0);
    cudaStreamWaitEvent(s1, evFork, 0);

    // s0: conv path (dominant)
    wfrag_kernel<<<(72 * 1024 + 255) / 256, 256>>>(conv_w);
    conv_mma_kernel<<<BBATCH * MT, 256>>>(vis);

    // s1: everything independent of conv
    sigma_v<<<(1152 + 255) / 256, 256, 0, s1>>>(conv_w, conv_u, 128, 1152, 0);
    sigma_t<<<(128 + 7) / 8, 256, 0, s1>>>(conv_w, 128, 1152, 0);
    deg_kernel<<<(NE + 255) / 256, 256, 0, s1>>>(ei);
    dis_kernel<<<(NN + 255) / 256, 256, 0, s1>>>();
    xw_kernel<<<NN / 8, 128, 0, s1>>>(topo, gcn_w);
    scatter_kernel<<<NE / 8, 256, 0, s1>>>(ei);
    {
        dim3 g(BBATCH, 4);
        topo_pool_kernel<<<g, 128, 0, s1>>>(batch, gcn_b);
    }
    sigma_v<<<(512 + 255) / 256, 256, 0, s1>>>(fcv_w, fcv_u, 256, 512, 1);
    sigma_t<<<(256 + 7) / 8, 256, 0, s1>>>(fcv_w, 256, 512, 1);
    sigma_v<<<(128 + 255) / 256, 256, 0, s1>>>(fct_w, fct_u, 256, 128, 2);
    sigma_t<<<(256 + 7) / 8, 256, 0, s1>>>(fct_w, 256, 128, 2);
    transpose_fcv<<<(256 * 512 + 255) / 256, 256, 0, s1>>>(fcv_w);
    transpose_fct<<<(256 * 128 + 255) / 256, 256, 0, s1>>>(fct_w);
    cudaEventRecord(evJoin, s1);

    // join on s0, then epilogue chain
    cudaStreamWaitEvent(0, evJoin, 0);
    vis_reduce_kernel<<<BBATCH, 512>>>(conv_b);
    vis_score_kernel<<<BBATCH, 256>>>(fcv_b, out);
    topo_score_kernel<<<BBATCH, 256>>>(fct_b, out);

    cudaEventDestroy(evFork);
    cudaEventDestroy(evJoin);
    cudaStreamDestroy(s1);
}